// round 7
// baseline (speedup 1.0000x reference)
#include <cuda_runtime.h>
#include <math.h>

#define NUM_C 1000
#define DIMS  256
#define NMAX  262144
#define CAP   512      // per-class slot capacity (mean 262, sd ~16)
#define TI_N  16       // 64-row A tiles
#define TJ_N  32       // 32-col B tiles
#define GRID_GEMM 272  // sum over ti of (32 - 2*ti)

// ---- device scratch ----
__device__ int   g_cursor[NUM_C];
__device__ int   g_idx[NUM_C * CAP];
__device__ float g_mn[NUM_C * DIMS];   // L2-normalized class means
__device__ int   g_maxkey;             // float-as-int key of (max_dot + 4.0f)
__device__ int   g_done;               // gemm completion ticket

// ---------------------------------------------------------------------------
__global__ void init_k() {
    int i = blockIdx.x * blockDim.x + threadIdx.x;
    if (i < NUM_C) g_cursor[i] = i * CAP;
    if (i == 0) { g_maxkey = 0; g_done = 0; }
}

__global__ void scatter_k(const int* __restrict__ labels, int n) {
    int i = blockIdx.x * blockDim.x + threadIdx.x;
    if (i < n) {
        int lab = labels[i];
        int pos = atomicAdd(&g_cursor[lab], 1);
        g_idx[pos] = i;
    }
}

// One CTA per class. Thread t = (quad = t>>6, col4 = t&63). (R4-proven)
__global__ void __launch_bounds__(256) gather_k(const float* __restrict__ f) {
    int c = blockIdx.x;
    int t = threadIdx.x;
    int beg = c * CAP;
    int cnt = g_cursor[c] - beg;
    int quad = t >> 6;
    int col  = t & 63;

    __shared__ int    sidx[256];
    __shared__ float4 sacc[256];
    __shared__ float  wsum[8];
    __shared__ float  sinv;

    const float4* f4 = (const float4*)f;
    float4 acc = make_float4(0.f, 0.f, 0.f, 0.f);

    for (int base = 0; base < cnt; base += 256) {
        int m = cnt - base; if (m > 256) m = 256;
        __syncthreads();
        if (t < m) sidx[t] = g_idx[beg + base + t];
        __syncthreads();
        int r = quad;
        for (; r + 12 < m; r += 16) {
            float4 v0 = f4[(long)sidx[r     ] * 64 + col];
            float4 v1 = f4[(long)sidx[r +  4] * 64 + col];
            float4 v2 = f4[(long)sidx[r +  8] * 64 + col];
            float4 v3 = f4[(long)sidx[r + 12] * 64 + col];
            acc.x += v0.x + v1.x + v2.x + v3.x;
            acc.y += v0.y + v1.y + v2.y + v3.y;
            acc.z += v0.z + v1.z + v2.z + v3.z;
            acc.w += v0.w + v1.w + v2.w + v3.w;
        }
        for (; r < m; r += 4) {
            float4 v = f4[(long)sidx[r] * 64 + col];
            acc.x += v.x; acc.y += v.y; acc.z += v.z; acc.w += v.w;
        }
    }

    sacc[t] = acc;
    __syncthreads();

    float4 mean = make_float4(0.f, 0.f, 0.f, 0.f);
    float ss = 0.f;
    if (t < 64) {
        float4 a = sacc[t], b = sacc[t + 64], c2 = sacc[t + 128], d = sacc[t + 192];
        float inv = 1.0f / (float)((cnt > 0) ? cnt : 1);
        mean.x = (a.x + b.x + c2.x + d.x) * inv;
        mean.y = (a.y + b.y + c2.y + d.y) * inv;
        mean.z = (a.z + b.z + c2.z + d.z) * inv;
        mean.w = (a.w + b.w + c2.w + d.w) * inv;
        ss = mean.x * mean.x + mean.y * mean.y + mean.z * mean.z + mean.w * mean.w;
    }
    #pragma unroll
    for (int o = 16; o > 0; o >>= 1) ss += __shfl_xor_sync(0xffffffffu, ss, o);
    if ((t & 31) == 0) wsum[t >> 5] = ss;
    __syncthreads();
    if (t == 0) {
        float tot = 0.f;
        #pragma unroll
        for (int w = 0; w < 8; w++) tot += wsum[w];
        sinv = (tot > 0.f) ? rsqrtf(tot) : 0.f;
    }
    __syncthreads();
    if (t < 64) {
        float s = sinv;
        float4 o4 = make_float4(mean.x * s, mean.y * s, mean.z * s, mean.w * s);
        ((float4*)g_mn)[(long)c * 64 + t] = o4;
    }
}

// Gram-max, 64x32 tiles (As 64KB + Bs 32KB = 96KB smem -> 2 CTAs/SM).
// Microtile per thread: rows {tx+16i, i<4} x cols {ty, ty+16}. XOR swizzle as before;
// note (ty+16)&7 == ty&7 so both B columns share one swizzle key.
// Tile (ti,tj) kept iff it can contain a strict-upper pair: tj >= 2*ti -> 272 CTAs.
// Last CTA to finish computes the loss and writes the output (fused epilogue).
__global__ void __launch_bounds__(256, 2) gemmmax_k(float* out, int n_out) {
    extern __shared__ float4 sm4[];
    float4* As = sm4;            // 64 rows * 64 chunks
    float4* Bs = sm4 + 64 * 64;  // 32 rows * 64 chunks

    int b = blockIdx.x;
    int ti = 0;
    int len = TJ_N;              // 32 - 2*ti
    while (b >= len) { b -= len; ti++; len -= 2; }
    int tj = 2 * ti + b;

    int t = threadIdx.x;
    const float4* mn4 = (const float4*)g_mn;

    #pragma unroll
    for (int p = 0; p < 16; p++) {
        int idx = p * 256 + t;
        int r = idx >> 6;
        int kc = idx & 63;
        int rA = ti * 64 + r;
        float4 va = (rA < NUM_C) ? mn4[(long)rA * 64 + kc] : make_float4(0.f,0.f,0.f,0.f);
        As[r * 64 + (kc ^ (r & 7))] = va;
    }
    #pragma unroll
    for (int p = 0; p < 8; p++) {
        int idx = p * 256 + t;
        int r = idx >> 6;            // 0..31
        int kc = idx & 63;
        int rB = tj * 32 + r;
        float4 vb = (rB < NUM_C) ? mn4[(long)rB * 64 + kc] : make_float4(0.f,0.f,0.f,0.f);
        Bs[r * 64 + (kc ^ (r & 7))] = vb;
    }
    __syncthreads();

    int tx = t & 15, ty = t >> 4;
    int sa = tx & 7, sb = ty & 7;
    float cc[4][2];
    #pragma unroll
    for (int i = 0; i < 4; i++) { cc[i][0] = 0.f; cc[i][1] = 0.f; }

    #pragma unroll 8
    for (int k4 = 0; k4 < 64; k4++) {
        int ka = k4 ^ sa;
        int kb = k4 ^ sb;
        float4 a0 = As[(tx     ) * 64 + ka];
        float4 a1 = As[(tx + 16) * 64 + ka];
        float4 a2 = As[(tx + 32) * 64 + ka];
        float4 a3 = As[(tx + 48) * 64 + ka];
        float4 b0 = Bs[(ty     ) * 64 + kb];
        float4 b1 = Bs[(ty + 16) * 64 + kb];
        float4 av[4] = {a0, a1, a2, a3};
        float4 bv[2] = {b0, b1};
        #pragma unroll
        for (int i = 0; i < 4; i++)
            #pragma unroll
            for (int j = 0; j < 2; j++) {
                cc[i][j] += av[i].x * bv[j].x;
                cc[i][j] += av[i].y * bv[j].y;
                cc[i][j] += av[i].z * bv[j].z;
                cc[i][j] += av[i].w * bv[j].w;
            }
    }

    // strict upper triangle only (gi < gj < NUM_C implies gi valid)
    float lm = -4.0f;
    #pragma unroll
    for (int i = 0; i < 4; i++) {
        int gi = ti * 64 + tx + 16 * i;
        #pragma unroll
        for (int j = 0; j < 2; j++) {
            int gj = tj * 32 + ty + 16 * j;
            if (gi < gj && gj < NUM_C) lm = fmaxf(lm, cc[i][j]);
        }
    }
    #pragma unroll
    for (int o = 16; o > 0; o >>= 1) lm = fmaxf(lm, __shfl_xor_sync(0xffffffffu, lm, o));
    __shared__ float wm[8];
    if ((t & 31) == 0) wm[t >> 5] = lm;
    __syncthreads();
    if (t == 0) {
        float m = wm[0];
        #pragma unroll
        for (int w = 1; w < 8; w++) m = fmaxf(m, wm[w]);
        atomicMax(&g_maxkey, __float_as_int(m + 4.0f));
        __threadfence();
        int ticket = atomicAdd(&g_done, 1);
        if (ticket == gridDim.x - 1) {
            float maxd = __int_as_float(*(volatile int*)&g_maxkey) - 4.0f;
            maxd = fminf(fmaxf(maxd, -1.f), 1.f);
            float mind = 1.0f - maxd;
            float loss = logf(1.0f / (mind + 1e-6f) + 1.0f);
            for (int i = 0; i < n_out; i++) out[i] = loss;
        }
    }
}

// ---------------------------------------------------------------------------
extern "C" void kernel_launch(void* const* d_in, const int* in_sizes, int n_in,
                              void* d_out, int out_size) {
    const float* features = (const float*)d_in[0];
    const int*   labels   = (const int*)d_in[1];
    int n = in_sizes[1];

    const int smem_gemm = (64 + 32) * 64 * (int)sizeof(float4); // 98304 B
    cudaFuncSetAttribute(gemmmax_k, cudaFuncAttributeMaxDynamicSharedMemorySize, smem_gemm);

    init_k<<<4, 256>>>();
    scatter_k<<<(n + 255) / 256, 256>>>(labels, n);
    gather_k<<<NUM_C, 256>>>(features);
    gemmmax_k<<<GRID_GEMM, 256, smem_gemm>>>((float*)d_out, out_size);
}

// round 9
// speedup vs baseline: 1.0500x; 1.0500x over previous
#include <cuda_runtime.h>
#include <math.h>

#define NUM_C 1000
#define DIMS  256
#define NMAX  262144
#define CAP   512      // per-class slot capacity (mean 262, sd ~16)
#define TILES 16       // ceil(1000/64)

typedef unsigned long long u64;

// ---- device scratch ----
__device__ int   g_cursor[NUM_C];
__device__ int   g_idx[NUM_C * CAP];
__device__ float g_mn[NUM_C * DIMS];   // L2-normalized class means
__device__ int   g_maxkey;             // float-as-int key of (max_dot + 4.0f)
__device__ int   g_done;               // gemm completion ticket

// packed dual-FMA: acc.{lo,hi} += a.{lo,hi} * b.{lo,hi}  (2x f32 per issue slot)
__device__ __forceinline__ void ffma2(u64& acc, u64 a, u64 b) {
    asm("fma.rn.f32x2 %0, %1, %2, %0;" : "+l"(acc) : "l"(a), "l"(b));
}
__device__ __forceinline__ float f32x2_sum(u64 v) {
    float lo, hi;
    asm("mov.b64 {%0, %1}, %2;" : "=f"(lo), "=f"(hi) : "l"(v));
    return lo + hi;
}

// ---------------------------------------------------------------------------
__global__ void init_k() {
    int i = blockIdx.x * blockDim.x + threadIdx.x;
    if (i < NUM_C) g_cursor[i] = i * CAP;
    if (i == 0) { g_maxkey = 0; g_done = 0; }
}

__global__ void scatter_k(const int* __restrict__ labels, int n) {
    int i = blockIdx.x * blockDim.x + threadIdx.x;
    if (i < n) {
        int lab = labels[i];
        int pos = atomicAdd(&g_cursor[lab], 1);
        g_idx[pos] = i;
    }
}

// One CTA per class. Thread t = (quad = t>>6, col4 = t&63). (R4-proven)
__global__ void __launch_bounds__(256) gather_k(const float* __restrict__ f) {
    int c = blockIdx.x;
    int t = threadIdx.x;
    int beg = c * CAP;
    int cnt = g_cursor[c] - beg;
    int quad = t >> 6;
    int col  = t & 63;

    __shared__ int    sidx[256];
    __shared__ float4 sacc[256];
    __shared__ float  wsum[8];
    __shared__ float  sinv;

    const float4* f4 = (const float4*)f;
    float4 acc = make_float4(0.f, 0.f, 0.f, 0.f);

    for (int base = 0; base < cnt; base += 256) {
        int m = cnt - base; if (m > 256) m = 256;
        __syncthreads();
        if (t < m) sidx[t] = g_idx[beg + base + t];
        __syncthreads();
        int r = quad;
        for (; r + 12 < m; r += 16) {
            float4 v0 = f4[(long)sidx[r     ] * 64 + col];
            float4 v1 = f4[(long)sidx[r +  4] * 64 + col];
            float4 v2 = f4[(long)sidx[r +  8] * 64 + col];
            float4 v3 = f4[(long)sidx[r + 12] * 64 + col];
            acc.x += v0.x + v1.x + v2.x + v3.x;
            acc.y += v0.y + v1.y + v2.y + v3.y;
            acc.z += v0.z + v1.z + v2.z + v3.z;
            acc.w += v0.w + v1.w + v2.w + v3.w;
        }
        for (; r < m; r += 4) {
            float4 v = f4[(long)sidx[r] * 64 + col];
            acc.x += v.x; acc.y += v.y; acc.z += v.z; acc.w += v.w;
        }
    }

    sacc[t] = acc;
    __syncthreads();

    float4 mean = make_float4(0.f, 0.f, 0.f, 0.f);
    float ss = 0.f;
    if (t < 64) {
        float4 a = sacc[t], b = sacc[t + 64], c2 = sacc[t + 128], d = sacc[t + 192];
        float inv = 1.0f / (float)((cnt > 0) ? cnt : 1);
        mean.x = (a.x + b.x + c2.x + d.x) * inv;
        mean.y = (a.y + b.y + c2.y + d.y) * inv;
        mean.z = (a.z + b.z + c2.z + d.z) * inv;
        mean.w = (a.w + b.w + c2.w + d.w) * inv;
        ss = mean.x * mean.x + mean.y * mean.y + mean.z * mean.z + mean.w * mean.w;
    }
    #pragma unroll
    for (int o = 16; o > 0; o >>= 1) ss += __shfl_xor_sync(0xffffffffu, ss, o);
    if ((t & 31) == 0) wsum[t >> 5] = ss;
    __syncthreads();
    if (t == 0) {
        float tot = 0.f;
        #pragma unroll
        for (int w = 0; w < 8; w++) tot += wsum[w];
        sinv = (tot > 0.f) ? rsqrtf(tot) : 0.f;
    }
    __syncthreads();
    if (t < 64) {
        float s = sinv;
        float4 o4 = make_float4(mean.x * s, mean.y * s, mean.z * s, mean.w * s);
        ((float4*)g_mn)[(long)c * 64 + t] = o4;
    }
}

// Gram-max, R6-proven shape: 64x64 tile, 136 upper-tri CTAs, XOR-swizzled smem,
// microtile rows {tx+16i} x cols {ty+16j}. Inner product uses packed
// fma.rn.f32x2: one u64 accumulator per (i,j), 2 packed FMAs per k4.
// Last CTA to finish computes the loss (fused epilogue).
__global__ void __launch_bounds__(256, 1) gemmmax_k(float* out, int n_out) {
    extern __shared__ float4 sm4[];
    float4* As = sm4;          // 64 rows * 64 chunks
    float4* Bs = sm4 + 64 * 64;

    int b = blockIdx.x;
    int ti = 0, rl = TILES;
    while (b >= rl) { b -= rl; ti++; rl--; }
    int tj = ti + b;

    int t = threadIdx.x;
    const float4* mn4 = (const float4*)g_mn;

    #pragma unroll
    for (int p = 0; p < 16; p++) {
        int idx = p * 256 + t;
        int r = idx >> 6;
        int kc = idx & 63;
        int rA = ti * 64 + r;
        int rB = tj * 64 + r;
        float4 va = (rA < NUM_C) ? mn4[(long)rA * 64 + kc] : make_float4(0.f,0.f,0.f,0.f);
        float4 vb = (rB < NUM_C) ? mn4[(long)rB * 64 + kc] : make_float4(0.f,0.f,0.f,0.f);
        int sw = kc ^ (r & 7);
        As[r * 64 + sw] = va;
        Bs[r * 64 + sw] = vb;
    }
    __syncthreads();

    int tx = t & 15, ty = t >> 4;
    int sa = tx & 7, sb = ty & 7;

    const ulonglong2* As2 = (const ulonglong2*)As;   // same 16B chunks, as (xy, zw) u64 pairs
    const ulonglong2* Bs2 = (const ulonglong2*)Bs;

    u64 cc[4][4];
    #pragma unroll
    for (int i = 0; i < 4; i++)
        #pragma unroll
        for (int j = 0; j < 4; j++) cc[i][j] = 0ull;   // (0.0f, 0.0f)

    #pragma unroll 8
    for (int k4 = 0; k4 < 64; k4++) {
        int ka = k4 ^ sa;
        int kb = k4 ^ sb;
        ulonglong2 a0 = As2[(tx     ) * 64 + ka];
        ulonglong2 a1 = As2[(tx + 16) * 64 + ka];
        ulonglong2 a2 = As2[(tx + 32) * 64 + ka];
        ulonglong2 a3 = As2[(tx + 48) * 64 + ka];
        ulonglong2 b0 = Bs2[(ty     ) * 64 + kb];
        ulonglong2 b1 = Bs2[(ty + 16) * 64 + kb];
        ulonglong2 b2 = Bs2[(ty + 32) * 64 + kb];
        ulonglong2 b3 = Bs2[(ty + 48) * 64 + kb];
        ulonglong2 av[4] = {a0, a1, a2, a3};
        ulonglong2 bv[4] = {b0, b1, b2, b3};
        #pragma unroll
        for (int i = 0; i < 4; i++)
            #pragma unroll
            for (int j = 0; j < 4; j++) {
                ffma2(cc[i][j], av[i].x, bv[j].x);   // x*x, y*y lanes
                ffma2(cc[i][j], av[i].y, bv[j].y);   // z*z, w*w lanes
            }
    }

    // strict upper triangle only
    float lm = -4.0f;
    #pragma unroll
    for (int i = 0; i < 4; i++) {
        int gi = ti * 64 + tx + 16 * i;
        #pragma unroll
        for (int j = 0; j < 4; j++) {
            int gj = tj * 64 + ty + 16 * j;
            if (gi < gj && gj < NUM_C) lm = fmaxf(lm, f32x2_sum(cc[i][j]));
        }
    }
    #pragma unroll
    for (int o = 16; o > 0; o >>= 1) lm = fmaxf(lm, __shfl_xor_sync(0xffffffffu, lm, o));
    __shared__ float wm[8];
    if ((t & 31) == 0) wm[t >> 5] = lm;
    __syncthreads();
    if (t == 0) {
        float m = wm[0];
        #pragma unroll
        for (int w = 1; w < 8; w++) m = fmaxf(m, wm[w]);
        atomicMax(&g_maxkey, __float_as_int(m + 4.0f));
        __threadfence();
        int ticket = atomicAdd(&g_done, 1);
        if (ticket == gridDim.x - 1) {
            float maxd = __int_as_float(*(volatile int*)&g_maxkey) - 4.0f;
            maxd = fminf(fmaxf(maxd, -1.f), 1.f);
            float mind = 1.0f - maxd;
            float loss = logf(1.0f / (mind + 1e-6f) + 1.0f);
            for (int i = 0; i < n_out; i++) out[i] = loss;
        }
    }
}

// ---------------------------------------------------------------------------
extern "C" void kernel_launch(void* const* d_in, const int* in_sizes, int n_in,
                              void* d_out, int out_size) {
    const float* features = (const float*)d_in[0];
    const int*   labels   = (const int*)d_in[1];
    int n = in_sizes[1];

    const int smem_gemm = 2 * 64 * 64 * (int)sizeof(float4); // 131072 B
    cudaFuncSetAttribute(gemmmax_k, cudaFuncAttributeMaxDynamicSharedMemorySize, smem_gemm);

    init_k<<<4, 256>>>();
    scatter_k<<<(n + 255) / 256, 256>>>(labels, n);
    gather_k<<<NUM_C, 256>>>(features);
    gemmmax_k<<<TILES * (TILES + 1) / 2, 256, smem_gemm>>>((float*)d_out, out_size);
}

// round 10
// speedup vs baseline: 1.1121x; 1.0592x over previous
#include <cuda_runtime.h>
#include <cuda_bf16.h>
#include <math.h>

#define NUM_C 1000
#define DIMS  256
#define NMAX  262144
#define CAP   512      // per-class slot capacity (mean 262, sd ~16)
#define TILES 16       // ceil(1000/64)
#define SROW  132      // smem row stride in 32-bit words (128 data + 4 pad)

// ---- device scratch ----
__device__ int      g_cursor[NUM_C];
__device__ int      g_idx[NUM_C * CAP];
__device__ unsigned g_hi[NUM_C * 128];   // bf16x2 hi plane of normalized means
__device__ unsigned g_lo[NUM_C * 128];   // bf16x2 lo plane
__device__ int      g_maxkey;            // float-as-int key of (max_dot + 4.0f)
__device__ int      g_done;              // gram completion ticket

__device__ __forceinline__ void mma_bf16(float& c0, float& c1, float& c2, float& c3,
                                         unsigned a0, unsigned a1, unsigned a2, unsigned a3,
                                         unsigned b0, unsigned b1) {
    asm("mma.sync.aligned.m16n8k16.row.col.f32.bf16.bf16.f32 "
        "{%0,%1,%2,%3}, {%4,%5,%6,%7}, {%8,%9}, {%0,%1,%2,%3};"
        : "+f"(c0), "+f"(c1), "+f"(c2), "+f"(c3)
        : "r"(a0), "r"(a1), "r"(a2), "r"(a3), "r"(b0), "r"(b1));
}

// ---------------------------------------------------------------------------
__global__ void init_k() {
    int i = blockIdx.x * blockDim.x + threadIdx.x;
    if (i < NUM_C) g_cursor[i] = i * CAP;
    if (i == 0) { g_maxkey = 0; g_done = 0; }
}

__global__ void scatter_k(const int* __restrict__ labels, int n) {
    int i = blockIdx.x * blockDim.x + threadIdx.x;
    if (i < n) {
        int lab = labels[i];
        int pos = atomicAdd(&g_cursor[lab], 1);
        g_idx[pos] = i;
    }
}

// One CTA per class (R4-proven body). Epilogue emits split-bf16 hi/lo planes.
__global__ void __launch_bounds__(256) gather_k(const float* __restrict__ f) {
    int c = blockIdx.x;
    int t = threadIdx.x;
    int beg = c * CAP;
    int cnt = g_cursor[c] - beg;
    int quad = t >> 6;
    int col  = t & 63;

    __shared__ int    sidx[256];
    __shared__ float4 sacc[256];
    __shared__ float  wsum[8];
    __shared__ float  sinv;

    const float4* f4 = (const float4*)f;
    float4 acc = make_float4(0.f, 0.f, 0.f, 0.f);

    for (int base = 0; base < cnt; base += 256) {
        int m = cnt - base; if (m > 256) m = 256;
        __syncthreads();
        if (t < m) sidx[t] = g_idx[beg + base + t];
        __syncthreads();
        int r = quad;
        for (; r + 12 < m; r += 16) {
            float4 v0 = f4[(long)sidx[r     ] * 64 + col];
            float4 v1 = f4[(long)sidx[r +  4] * 64 + col];
            float4 v2 = f4[(long)sidx[r +  8] * 64 + col];
            float4 v3 = f4[(long)sidx[r + 12] * 64 + col];
            acc.x += v0.x + v1.x + v2.x + v3.x;
            acc.y += v0.y + v1.y + v2.y + v3.y;
            acc.z += v0.z + v1.z + v2.z + v3.z;
            acc.w += v0.w + v1.w + v2.w + v3.w;
        }
        for (; r < m; r += 4) {
            float4 v = f4[(long)sidx[r] * 64 + col];
            acc.x += v.x; acc.y += v.y; acc.z += v.z; acc.w += v.w;
        }
    }

    sacc[t] = acc;
    __syncthreads();

    float4 mean = make_float4(0.f, 0.f, 0.f, 0.f);
    float ss = 0.f;
    if (t < 64) {
        float4 a = sacc[t], b = sacc[t + 64], c2 = sacc[t + 128], d = sacc[t + 192];
        float inv = 1.0f / (float)((cnt > 0) ? cnt : 1);
        mean.x = (a.x + b.x + c2.x + d.x) * inv;
        mean.y = (a.y + b.y + c2.y + d.y) * inv;
        mean.z = (a.z + b.z + c2.z + d.z) * inv;
        mean.w = (a.w + b.w + c2.w + d.w) * inv;
        ss = mean.x * mean.x + mean.y * mean.y + mean.z * mean.z + mean.w * mean.w;
    }
    #pragma unroll
    for (int o = 16; o > 0; o >>= 1) ss += __shfl_xor_sync(0xffffffffu, ss, o);
    if ((t & 31) == 0) wsum[t >> 5] = ss;
    __syncthreads();
    if (t == 0) {
        float tot = 0.f;
        #pragma unroll
        for (int w = 0; w < 8; w++) tot += wsum[w];
        sinv = (tot > 0.f) ? rsqrtf(tot) : 0.f;
    }
    __syncthreads();
    if (t < 64) {
        float s = sinv;
        float v[4] = {mean.x * s, mean.y * s, mean.z * s, mean.w * s};
        unsigned h[4], l[4];
        #pragma unroll
        for (int i = 0; i < 4; i++) {
            __nv_bfloat16 hb = __float2bfloat16(v[i]);
            float res = v[i] - __bfloat162float(hb);
            __nv_bfloat16 lb = __float2bfloat16(res);
            h[i] = __bfloat16_as_ushort(hb);
            l[i] = __bfloat16_as_ushort(lb);
        }
        // word w holds cols {2w, 2w+1}: low half = even col
        g_hi[c * 128 + 2 * t    ] = h[0] | (h[1] << 16);
        g_hi[c * 128 + 2 * t + 1] = h[2] | (h[3] << 16);
        g_lo[c * 128 + 2 * t    ] = l[0] | (l[1] << 16);
        g_lo[c * 128 + 2 * t + 1] = l[2] | (l[3] << 16);
    }
}

// Tensor-core gram-max: 64x64 tiles, 136 upper-tri CTAs, 8 warps (4 row x 2 col),
// each warp: 16 rows x 32 cols (4 n8 tiles). Split-bf16 3-term mma per k16 step.
// smem: 4 planes of [64][SROW] words; fragment reads bank-conflict-free via pad.
__global__ void __launch_bounds__(256, 1) grammax_k(float* out, int n_out) {
    extern __shared__ unsigned smw[];
    unsigned* sAh = smw;
    unsigned* sAl = smw + 64 * SROW;
    unsigned* sBh = smw + 2 * 64 * SROW;
    unsigned* sBl = smw + 3 * 64 * SROW;

    int b = blockIdx.x;
    int ti = 0, rl = TILES;
    while (b >= rl) { b -= rl; ti++; rl--; }
    int tj = ti + b;

    int t = threadIdx.x;

    // stage: each plane 64 rows x 128 words, coalesced loads, conflict-free stores
    #pragma unroll
    for (int p = 0; p < 32; p++) {
        int idx = p * 256 + t;          // 0..8191
        int r = idx >> 7;               // 0..63
        int cw = idx & 127;
        int rA = ti * 64 + r;
        int rB = tj * 64 + r;
        unsigned ah = (rA < NUM_C) ? g_hi[rA * 128 + cw] : 0u;
        unsigned al = (rA < NUM_C) ? g_lo[rA * 128 + cw] : 0u;
        unsigned bh = (rB < NUM_C) ? g_hi[rB * 128 + cw] : 0u;
        unsigned bl = (rB < NUM_C) ? g_lo[rB * 128 + cw] : 0u;
        sAh[r * SROW + cw] = ah;
        sAl[r * SROW + cw] = al;
        sBh[r * SROW + cw] = bh;
        sBl[r * SROW + cw] = bl;
    }
    __syncthreads();

    int w    = t >> 5;       // warp 0..7
    int lane = t & 31;
    int wrow = (w & 3) * 16;            // warp's row base in tile
    int wcol = (w >> 2) * 32;           // warp's col base in tile
    int lr   = lane >> 2;               // 0..7
    int lk   = lane & 3;                // k word within k8

    float acc[4][4];
    #pragma unroll
    for (int tn = 0; tn < 4; tn++)
        #pragma unroll
        for (int i = 0; i < 4; i++) acc[tn][i] = 0.f;

    #pragma unroll
    for (int kk = 0; kk < 16; kk++) {
        int kb = kk * 8;                // base k word (k16 = 8 words)
        int r0 = wrow + lr;
        unsigned ah0 = sAh[ r0      * SROW + kb + lk    ];
        unsigned ah1 = sAh[(r0 + 8) * SROW + kb + lk    ];
        unsigned ah2 = sAh[ r0      * SROW + kb + lk + 4];
        unsigned ah3 = sAh[(r0 + 8) * SROW + kb + lk + 4];
        unsigned al0 = sAl[ r0      * SROW + kb + lk    ];
        unsigned al1 = sAl[(r0 + 8) * SROW + kb + lk    ];
        unsigned al2 = sAl[ r0      * SROW + kb + lk + 4];
        unsigned al3 = sAl[(r0 + 8) * SROW + kb + lk + 4];
        #pragma unroll
        for (int tn = 0; tn < 4; tn++) {
            int nc = wcol + tn * 8 + lr;
            unsigned bh0 = sBh[nc * SROW + kb + lk    ];
            unsigned bh1 = sBh[nc * SROW + kb + lk + 4];
            unsigned bl0 = sBl[nc * SROW + kb + lk    ];
            unsigned bl1 = sBl[nc * SROW + kb + lk + 4];
            mma_bf16(acc[tn][0], acc[tn][1], acc[tn][2], acc[tn][3],
                     ah0, ah1, ah2, ah3, bh0, bh1);
            mma_bf16(acc[tn][0], acc[tn][1], acc[tn][2], acc[tn][3],
                     ah0, ah1, ah2, ah3, bl0, bl1);
            mma_bf16(acc[tn][0], acc[tn][1], acc[tn][2], acc[tn][3],
                     al0, al1, al2, al3, bh0, bh1);
        }
    }

    // mask to strict upper triangle, reduce max
    float lm = -4.0f;
    int gi0 = ti * 64 + wrow + lr;
    #pragma unroll
    for (int tn = 0; tn < 4; tn++) {
        int gj0 = tj * 64 + wcol + tn * 8 + 2 * lk;
        // acc[tn] = { (gi0,gj0), (gi0,gj0+1), (gi0+8,gj0), (gi0+8,gj0+1) }
        if (gi0     < gj0     && gj0     < NUM_C) lm = fmaxf(lm, acc[tn][0]);
        if (gi0     < gj0 + 1 && gj0 + 1 < NUM_C) lm = fmaxf(lm, acc[tn][1]);
        if (gi0 + 8 < gj0     && gj0     < NUM_C) lm = fmaxf(lm, acc[tn][2]);
        if (gi0 + 8 < gj0 + 1 && gj0 + 1 < NUM_C) lm = fmaxf(lm, acc[tn][3]);
    }
    #pragma unroll
    for (int o = 16; o > 0; o >>= 1) lm = fmaxf(lm, __shfl_xor_sync(0xffffffffu, lm, o));
    __shared__ float wm[8];
    if (lane == 0) wm[w] = lm;
    __syncthreads();
    if (t == 0) {
        float m = wm[0];
        #pragma unroll
        for (int q = 1; q < 8; q++) m = fmaxf(m, wm[q]);
        atomicMax(&g_maxkey, __float_as_int(m + 4.0f));
        __threadfence();
        int ticket = atomicAdd(&g_done, 1);
        if (ticket == gridDim.x - 1) {
            float maxd = __int_as_float(*(volatile int*)&g_maxkey) - 4.0f;
            maxd = fminf(fmaxf(maxd, -1.f), 1.f);
            float mind = 1.0f - maxd;
            float loss = logf(1.0f / (mind + 1e-6f) + 1.0f);
            for (int i = 0; i < n_out; i++) out[i] = loss;
        }
    }
}

// ---------------------------------------------------------------------------
extern "C" void kernel_launch(void* const* d_in, const int* in_sizes, int n_in,
                              void* d_out, int out_size) {
    const float* features = (const float*)d_in[0];
    const int*   labels   = (const int*)d_in[1];
    int n = in_sizes[1];

    const int smem_gram = 4 * 64 * SROW * (int)sizeof(unsigned); // 135168 B
    cudaFuncSetAttribute(grammax_k, cudaFuncAttributeMaxDynamicSharedMemorySize, smem_gram);

    init_k<<<4, 256>>>();
    scatter_k<<<(n + 255) / 256, 256>>>(labels, n);
    gather_k<<<NUM_C, 256>>>(features);
    grammax_k<<<TILES * (TILES + 1) / 2, 256, smem_gram>>>((float*)d_out, out_size);
}

// round 11
// speedup vs baseline: 1.1223x; 1.0092x over previous
#include <cuda_runtime.h>
#include <cuda_bf16.h>
#include <math.h>

#define NUM_C 1000
#define DIMS  256
#define NMAX  262144
#define CAP   512      // per-class slot capacity (mean 262, sd ~16)
#define TILES 16       // ceil(1000/64)
#define SROW  132      // smem row stride in 32-bit words (128 data + 4 pad)

// ---- device scratch ----
__device__ int      g_cursor[NUM_C];
__device__ int      g_idx[NUM_C * CAP];
__device__ unsigned g_hi[NUM_C * 128];   // bf16x2 hi plane of normalized means
__device__ unsigned g_lo[NUM_C * 128];   // bf16x2 lo plane
__device__ int      g_maxkey;            // float-as-int key of (max_dot + 4.0f)
__device__ int      g_done;              // gram completion ticket

__device__ __forceinline__ void mma_bf16(float& c0, float& c1, float& c2, float& c3,
                                         unsigned a0, unsigned a1, unsigned a2, unsigned a3,
                                         unsigned b0, unsigned b1) {
    asm("mma.sync.aligned.m16n8k16.row.col.f32.bf16.bf16.f32 "
        "{%0,%1,%2,%3}, {%4,%5,%6,%7}, {%8,%9}, {%0,%1,%2,%3};"
        : "+f"(c0), "+f"(c1), "+f"(c2), "+f"(c3)
        : "r"(a0), "r"(a1), "r"(a2), "r"(a3), "r"(b0), "r"(b1));
}

__device__ __forceinline__ void ldsm_x4(unsigned& r0, unsigned& r1, unsigned& r2, unsigned& r3,
                                        unsigned addr) {
    asm volatile("ldmatrix.sync.aligned.m8n8.x4.shared.b16 {%0,%1,%2,%3}, [%4];"
        : "=r"(r0), "=r"(r1), "=r"(r2), "=r"(r3) : "r"(addr));
}

__device__ __forceinline__ unsigned smem_u32(const void* p) {
    unsigned a;
    asm("{ .reg .u64 t; cvta.to.shared.u64 t, %1; cvt.u32.u64 %0, t; }" : "=r"(a) : "l"(p));
    return a;
}

// ---------------------------------------------------------------------------
__global__ void init_k() {
    int i = blockIdx.x * blockDim.x + threadIdx.x;
    if (i < NUM_C) g_cursor[i] = i * CAP;
    if (i == 0) { g_maxkey = 0; g_done = 0; }
}

__global__ void scatter_k(const int* __restrict__ labels, int n) {
    int i = blockIdx.x * blockDim.x + threadIdx.x;
    if (i < n) {
        int lab = labels[i];
        int pos = atomicAdd(&g_cursor[lab], 1);
        g_idx[pos] = i;
    }
}

// One CTA per class (R4-proven body). Epilogue emits split-bf16 hi/lo planes.
__global__ void __launch_bounds__(256) gather_k(const float* __restrict__ f) {
    int c = blockIdx.x;
    int t = threadIdx.x;
    int beg = c * CAP;
    int cnt = g_cursor[c] - beg;
    int quad = t >> 6;
    int col  = t & 63;

    __shared__ int    sidx[256];
    __shared__ float4 sacc[256];
    __shared__ float  wsum[8];
    __shared__ float  sinv;

    const float4* f4 = (const float4*)f;
    float4 acc = make_float4(0.f, 0.f, 0.f, 0.f);

    for (int base = 0; base < cnt; base += 256) {
        int m = cnt - base; if (m > 256) m = 256;
        __syncthreads();
        if (t < m) sidx[t] = g_idx[beg + base + t];
        __syncthreads();
        int r = quad;
        for (; r + 12 < m; r += 16) {
            float4 v0 = f4[(long)sidx[r     ] * 64 + col];
            float4 v1 = f4[(long)sidx[r +  4] * 64 + col];
            float4 v2 = f4[(long)sidx[r +  8] * 64 + col];
            float4 v3 = f4[(long)sidx[r + 12] * 64 + col];
            acc.x += v0.x + v1.x + v2.x + v3.x;
            acc.y += v0.y + v1.y + v2.y + v3.y;
            acc.z += v0.z + v1.z + v2.z + v3.z;
            acc.w += v0.w + v1.w + v2.w + v3.w;
        }
        for (; r < m; r += 4) {
            float4 v = f4[(long)sidx[r] * 64 + col];
            acc.x += v.x; acc.y += v.y; acc.z += v.z; acc.w += v.w;
        }
    }

    sacc[t] = acc;
    __syncthreads();

    float4 mean = make_float4(0.f, 0.f, 0.f, 0.f);
    float ss = 0.f;
    if (t < 64) {
        float4 a = sacc[t], b = sacc[t + 64], c2 = sacc[t + 128], d = sacc[t + 192];
        float inv = 1.0f / (float)((cnt > 0) ? cnt : 1);
        mean.x = (a.x + b.x + c2.x + d.x) * inv;
        mean.y = (a.y + b.y + c2.y + d.y) * inv;
        mean.z = (a.z + b.z + c2.z + d.z) * inv;
        mean.w = (a.w + b.w + c2.w + d.w) * inv;
        ss = mean.x * mean.x + mean.y * mean.y + mean.z * mean.z + mean.w * mean.w;
    }
    #pragma unroll
    for (int o = 16; o > 0; o >>= 1) ss += __shfl_xor_sync(0xffffffffu, ss, o);
    if ((t & 31) == 0) wsum[t >> 5] = ss;
    __syncthreads();
    if (t == 0) {
        float tot = 0.f;
        #pragma unroll
        for (int w = 0; w < 8; w++) tot += wsum[w];
        sinv = (tot > 0.f) ? rsqrtf(tot) : 0.f;
    }
    __syncthreads();
    if (t < 64) {
        float s = sinv;
        float v[4] = {mean.x * s, mean.y * s, mean.z * s, mean.w * s};
        unsigned h[4], l[4];
        #pragma unroll
        for (int i = 0; i < 4; i++) {
            __nv_bfloat16 hb = __float2bfloat16(v[i]);
            float res = v[i] - __bfloat162float(hb);
            __nv_bfloat16 lb = __float2bfloat16(res);
            h[i] = __bfloat16_as_ushort(hb);
            l[i] = __bfloat16_as_ushort(lb);
        }
        g_hi[c * 128 + 2 * t    ] = h[0] | (h[1] << 16);
        g_hi[c * 128 + 2 * t + 1] = h[2] | (h[3] << 16);
        g_lo[c * 128 + 2 * t    ] = l[0] | (l[1] << 16);
        g_lo[c * 128 + 2 * t + 1] = l[2] | (l[3] << 16);
    }
}

// Tensor-core gram-max with ldmatrix fragment loads.
// 64x64 tiles, 136 upper-tri CTAs, 8 warps (4 row x 2 col), warp: 16 rows x 32 cols.
// Split-bf16 3-term mma. Per k16 step: 6 ldmatrix.x4 + 12 mma (was 24 LDS + 12 mma).
__global__ void __launch_bounds__(256, 1) grammax_k(float* out, int n_out) {
    extern __shared__ unsigned smw[];
    unsigned* sAh = smw;
    unsigned* sAl = smw + 64 * SROW;
    unsigned* sBh = smw + 2 * 64 * SROW;
    unsigned* sBl = smw + 3 * 64 * SROW;

    int b = blockIdx.x;
    int ti = 0, rl = TILES;
    while (b >= rl) { b -= rl; ti++; rl--; }
    int tj = ti + b;

    int t = threadIdx.x;

    // stage: 4 planes of 64 rows x 128 words; conflict-free via SROW pad
    #pragma unroll
    for (int p = 0; p < 32; p++) {
        int idx = p * 256 + t;
        int r = idx >> 7;
        int cw = idx & 127;
        int rA = ti * 64 + r;
        int rB = tj * 64 + r;
        unsigned ah = (rA < NUM_C) ? g_hi[rA * 128 + cw] : 0u;
        unsigned al = (rA < NUM_C) ? g_lo[rA * 128 + cw] : 0u;
        unsigned bh = (rB < NUM_C) ? g_hi[rB * 128 + cw] : 0u;
        unsigned bl = (rB < NUM_C) ? g_lo[rB * 128 + cw] : 0u;
        sAh[r * SROW + cw] = ah;
        sAl[r * SROW + cw] = al;
        sBh[r * SROW + cw] = bh;
        sBl[r * SROW + cw] = bl;
    }
    __syncthreads();

    int w    = t >> 5;
    int lane = t & 31;
    int wrow = (w & 3) * 16;
    int wcol = (w >> 2) * 32;
    int lr   = lane >> 2;     // for epilogue mapping
    int lk   = lane & 3;

    // ldmatrix per-lane addresses
    int lr8 = lane & 7, grp = lane >> 3;
    int aRow = wrow + lr8 + ((grp & 1) << 3);      // m0/m2: rows 0-7, m1/m3: rows 8-15
    int aK   = (grp >> 1) << 2;                    // m0/m1: k0-7, m2/m3: k8-15 (words)
    int bRow0 = wcol + lr8 + ((grp >> 1) << 3);    // m0/m1: n tile tn0, m2/m3: tn1
    int bK   = (grp & 1) << 2;                     // m0/m2: k0-7, m1/m3: k8-15

    unsigned uAhi  = smem_u32(sAh) + 4u * (aRow * SROW + aK);
    unsigned uAlo  = uAhi + 4u * 64 * SROW;
    unsigned uB0hi = smem_u32(sBh) + 4u * (bRow0 * SROW + bK);
    unsigned uB1hi = uB0hi + 4u * 16 * SROW;       // tn2/tn3 block (+16 n rows)
    unsigned uB0lo = uB0hi + 4u * 64 * SROW;
    unsigned uB1lo = uB1hi + 4u * 64 * SROW;

    float acc[4][4];
    #pragma unroll
    for (int tn = 0; tn < 4; tn++)
        #pragma unroll
        for (int i = 0; i < 4; i++) acc[tn][i] = 0.f;

    #pragma unroll
    for (int kk = 0; kk < 16; kk++) {
        unsigned ah0,ah1,ah2,ah3, al0,al1,al2,al3;
        ldsm_x4(ah0, ah1, ah2, ah3, uAhi);
        ldsm_x4(al0, al1, al2, al3, uAlo);
        unsigned b00h,b01h,b10h,b11h, b20h,b21h,b30h,b31h;
        ldsm_x4(b00h, b01h, b10h, b11h, uB0hi);    // tn0: {b0,b1}, tn1: {b0,b1}
        ldsm_x4(b20h, b21h, b30h, b31h, uB1hi);    // tn2, tn3
        unsigned b00l,b01l,b10l,b11l, b20l,b21l,b30l,b31l;
        ldsm_x4(b00l, b01l, b10l, b11l, uB0lo);
        ldsm_x4(b20l, b21l, b30l, b31l, uB1lo);

        mma_bf16(acc[0][0],acc[0][1],acc[0][2],acc[0][3], ah0,ah1,ah2,ah3, b00h,b01h);
        mma_bf16(acc[0][0],acc[0][1],acc[0][2],acc[0][3], ah0,ah1,ah2,ah3, b00l,b01l);
        mma_bf16(acc[0][0],acc[0][1],acc[0][2],acc[0][3], al0,al1,al2,al3, b00h,b01h);

        mma_bf16(acc[1][0],acc[1][1],acc[1][2],acc[1][3], ah0,ah1,ah2,ah3, b10h,b11h);
        mma_bf16(acc[1][0],acc[1][1],acc[1][2],acc[1][3], ah0,ah1,ah2,ah3, b10l,b11l);
        mma_bf16(acc[1][0],acc[1][1],acc[1][2],acc[1][3], al0,al1,al2,al3, b10h,b11h);

        mma_bf16(acc[2][0],acc[2][1],acc[2][2],acc[2][3], ah0,ah1,ah2,ah3, b20h,b21h);
        mma_bf16(acc[2][0],acc[2][1],acc[2][2],acc[2][3], ah0,ah1,ah2,ah3, b20l,b21l);
        mma_bf16(acc[2][0],acc[2][1],acc[2][2],acc[2][3], al0,al1,al2,al3, b20h,b21h);

        mma_bf16(acc[3][0],acc[3][1],acc[3][2],acc[3][3], ah0,ah1,ah2,ah3, b30h,b31h);
        mma_bf16(acc[3][0],acc[3][1],acc[3][2],acc[3][3], ah0,ah1,ah2,ah3, b30l,b31l);
        mma_bf16(acc[3][0],acc[3][1],acc[3][2],acc[3][3], al0,al1,al2,al3, b30h,b31h);

        uAhi += 32; uAlo += 32;
        uB0hi += 32; uB1hi += 32; uB0lo += 32; uB1lo += 32;
    }

    // mask to strict upper triangle, reduce max
    float lm = -4.0f;
    int gi0 = ti * 64 + wrow + lr;
    #pragma unroll
    for (int tn = 0; tn < 4; tn++) {
        int gj0 = tj * 64 + wcol + tn * 8 + 2 * lk;
        if (gi0     < gj0     && gj0     < NUM_C) lm = fmaxf(lm, acc[tn][0]);
        if (gi0     < gj0 + 1 && gj0 + 1 < NUM_C) lm = fmaxf(lm, acc[tn][1]);
        if (gi0 + 8 < gj0     && gj0     < NUM_C) lm = fmaxf(lm, acc[tn][2]);
        if (gi0 + 8 < gj0 + 1 && gj0 + 1 < NUM_C) lm = fmaxf(lm, acc[tn][3]);
    }
    #pragma unroll
    for (int o = 16; o > 0; o >>= 1) lm = fmaxf(lm, __shfl_xor_sync(0xffffffffu, lm, o));
    __shared__ float wm[8];
    if (lane == 0) wm[w] = lm;
    __syncthreads();
    if (t == 0) {
        float m = wm[0];
        #pragma unroll
        for (int q = 1; q < 8; q++) m = fmaxf(m, wm[q]);
        atomicMax(&g_maxkey, __float_as_int(m + 4.0f));
        __threadfence();
        int ticket = atomicAdd(&g_done, 1);
        if (ticket == gridDim.x - 1) {
            float maxd = __int_as_float(*(volatile int*)&g_maxkey) - 4.0f;
            maxd = fminf(fmaxf(maxd, -1.f), 1.f);
            float mind = 1.0f - maxd;
            float loss = logf(1.0f / (mind + 1e-6f) + 1.0f);
            for (int i = 0; i < n_out; i++) out[i] = loss;
        }
    }
}

// ---------------------------------------------------------------------------
extern "C" void kernel_launch(void* const* d_in, const int* in_sizes, int n_in,
                              void* d_out, int out_size) {
    const float* features = (const float*)d_in[0];
    const int*   labels   = (const int*)d_in[1];
    int n = in_sizes[1];

    const int smem_gram = 4 * 64 * SROW * (int)sizeof(unsigned); // 135168 B
    cudaFuncSetAttribute(grammax_k, cudaFuncAttributeMaxDynamicSharedMemorySize, smem_gram);

    init_k<<<4, 256>>>();
    scatter_k<<<(n + 255) / 256, 256>>>(labels, n);
    gather_k<<<NUM_C, 256>>>(features);
    grammax_k<<<TILES * (TILES + 1) / 2, 256, smem_gram>>>((float*)d_out, out_size);
}